// round 8
// baseline (speedup 1.0000x reference)
#include <cuda_runtime.h>
#include <math.h>

#define BB 32
#define TT 4096
#define FF 256
#define KSEL 409            // max(1, int(4096*0.1))
#define RPW 8               // rows per warp in kA
#define RPB 64              // rows per block in kA
#define NCHUNK (TT/RPB)     // 64
#define NS 16               // gather slices per batch
#define TSLICE (TT/NS)      // 256 rows per slice

__device__ float g_w[BB*TT];
__device__ float g_part[BB*NCHUNK*FF];
__device__ float g_corr[BB*NS*FF];
__device__ int   g_cnt[BB];           // zero-init; self-resetting

// ==== Kernel A: single-pass fused dot + weighted feature sum (register-only) ====
__global__ void __launch_bounds__(256, 6) kA(const float* __restrict__ x,
                                             const float* __restrict__ W,
                                             const float* __restrict__ bias) {
    __shared__ float4 sacc[8][64];
    const int c = blockIdx.x, b = blockIdx.y;
    const int tid = threadIdx.x;
    const int warp = tid >> 5, lane = tid & 31;

    const float4* wr = (const float4*)W;
    const float4 w0 = __ldg(&wr[lane]);
    const float4 w1 = __ldg(&wr[lane + 32]);
    const float bias0 = bias[0];

    const int row0 = c * RPB + warp * RPW;
    const float4* xg = (const float4*)(x + ((size_t)b*TT + row0) * FF);

    float4 ac0 = make_float4(0.f,0.f,0.f,0.f);
    float4 ac1 = make_float4(0.f,0.f,0.f,0.f);
    float wkeep = 0.f;

    #pragma unroll 4
    for (int r = 0; r < RPW; r++) {
        const float4 a0 = xg[(size_t)r*64 + lane];
        const float4 a1 = xg[(size_t)r*64 + 32 + lane];
        float s = a0.x*w0.x + a0.y*w0.y + a0.z*w0.z + a0.w*w0.w
                + a1.x*w1.x + a1.y*w1.y + a1.z*w1.z + a1.w*w1.w;
        #pragma unroll
        for (int o = 16; o; o >>= 1) s += __shfl_xor_sync(0xffffffffu, s, o);
        const float wv = __expf(tanhf(s + bias0) - 1.0f);  // shift by max=1
        if (lane == r) wkeep = wv;
        ac0.x += a0.x*wv; ac0.y += a0.y*wv; ac0.z += a0.z*wv; ac0.w += a0.w*wv;
        ac1.x += a1.x*wv; ac1.y += a1.y*wv; ac1.z += a1.z*wv; ac1.w += a1.w*wv;
    }
    if (lane < RPW) g_w[b*TT + row0 + lane] = wkeep;

    sacc[warp][lane]      = ac0;
    sacc[warp][32 + lane] = ac1;
    __syncthreads();

    const int f4 = tid & 63, h = tid >> 6;
    if (h == 0) {
        float4 s = sacc[0][f4];
        #pragma unroll
        for (int wdx = 1; wdx < 8; wdx++) {
            float4 t = sacc[wdx][f4];
            s.x += t.x; s.y += t.y; s.z += t.z; s.w += t.w;
        }
        ((float4*)g_part)[((size_t)b*NCHUNK + c)*64 + f4] = s;
    }
}

// ==== Kernel SG: redundant selection + t-sliced gather + last-block combine ====
__global__ void __launch_bounds__(256) kSG(const float* __restrict__ x,
                                           float* __restrict__ out) {
    __shared__ float    red[256];
    __shared__ unsigned cnt[32];
    __shared__ float    wsh[TSLICE];
    __shared__ float4   acc_sh[256];
    __shared__ int      lastflag;
    const int s = blockIdx.x, b = blockIdx.y, tid = threadIdx.x;
    const int lane = tid & 31;

    // full-batch keys: 16 per thread (w[b,:] is 16KB, L2-hot from kA)
    unsigned key[16];
    float zsum = 0.f;
    #pragma unroll
    for (int i = 0; i < 16; i++) {
        float w = g_w[b*TT + tid + i*256];
        key[i] = __float_as_uint(w);        // w in (e^-2,1]: bits order-preserving
        zsum += w;
    }
    red[tid] = zsum;
    if (tid < 32) cnt[tid] = 0;
    wsh[tid] = g_w[b*TT + s*TSLICE + tid];  // own slice for the gather
    __syncthreads();
    #pragma unroll
    for (int o = 128; o; o >>= 1) {
        if (tid < o) red[tid] += red[tid + o];
        __syncthreads();
    }
    const float invZ = 1.0f / red[0];

    // w in (e^-2,1]: bits 31,30=0, bits 29..25=11111 -> bisect bits 24..0
    unsigned prefix = 0x3E000000u;
    for (int bit = 24; bit >= 0; bit--) {
        const unsigned test = prefix | (1u << bit);
        unsigned c = 0;
        #pragma unroll
        for (int i = 0; i < 16; i++) c += (key[i] >= test);
        c = __reduce_add_sync(0xffffffffu, c);
        if (lane == 0) atomicAdd(&cnt[bit], c);
        __syncthreads();
        if (cnt[bit] >= KSEL) prefix = test;   // unique counter per bit
    }

    // gather: rows in own slice with bits(w) >= prefix (warp-uniform predicate)
    const int f4 = tid & 63;        // float4 feature group
    const int h  = tid >> 6;        // 0..3 row-phase
    const int t0 = s * TSLICE;
    const float4* xb4 = ((const float4*)(x + (size_t)b*TT*FF)) + f4;
    float4 a = make_float4(0.f,0.f,0.f,0.f);
    #pragma unroll 4
    for (int r = h; r < TSLICE; r += 4) {
        const float wv = wsh[r];
        if (__float_as_uint(wv) >= prefix) {
            const float4 v = xb4[(size_t)(t0 + r) * 64];
            a.x += v.x*wv; a.y += v.y*wv; a.z += v.z*wv; a.w += v.w*wv;
        }
    }
    acc_sh[tid] = a;
    __syncthreads();
    if (h == 0) {
        float4 v = acc_sh[f4];
        #pragma unroll
        for (int j = 1; j < 4; j++) {
            float4 t = acc_sh[j*64 + f4];
            v.x += t.x; v.y += t.y; v.z += t.z; v.w += t.w;
        }
        ((float4*)g_corr)[((size_t)b*NS + s)*64 + f4] = v;
    }
    // last block per batch does the final combine (fixed read order)
    __threadfence();
    __syncthreads();
    if (tid == 0) lastflag = (atomicAdd(&g_cnt[b], 1) == NS - 1);
    __syncthreads();
    if (lastflag) {
        const int f = tid;
        float s1 = 0.f, sc = 0.f;
        #pragma unroll 8
        for (int c = 0; c < NCHUNK; c++) s1 += g_part[(b*NCHUNK + c)*FF + f];
        #pragma unroll
        for (int ss = 0; ss < NS; ss++) sc += g_corr[(b*NS + ss)*FF + f];
        out[b*FF + f] = (s1 + 0.5f * sc) * invZ;
        if (tid == 0) g_cnt[b] = 0;         // reset for next graph replay
    }
}

extern "C" void kernel_launch(void* const* d_in, const int* in_sizes, int n_in,
                              void* d_out, int out_size) {
    const float* x    = (const float*)d_in[0];
    const float* W    = (const float*)d_in[1];
    const float* bias = (const float*)d_in[2];
    float* out = (float*)d_out;

    dim3 gA(NCHUNK, BB);
    kA<<<gA, 256>>>(x, W, bias);
    dim3 gS(NS, BB);
    kSG<<<gS, 256>>>(x, out);
}